// round 4
// baseline (speedup 1.0000x reference)
#include <cuda_runtime.h>
#include <math.h>

#define Bn 4
#define Tn 8192
#define Dn 512
#define Sn 16
#define PARTS 64   // 256 blocks / 4 batches in the G pass

typedef unsigned long long ull;

// Scratch (static device globals — allocation-free per harness rules)
__device__ float g_attn [Bn*Tn*Sn];          // 2 MB
__device__ float g_Gpart[Bn*PARTS*Sn*Dn];    // 8 MB
__device__ float g_G    [Bn*Sn*Dn];
__device__ float g_H    [Bn*Sn*Dn];
__device__ float g_M    [Bn*Sn*Dn];

// ---- packed f32x2 helpers (FFMA2: only reachable via PTX) ----
__device__ __forceinline__ ull fma2(ull a, ull b, ull c) {
    ull d; asm("fma.rn.f32x2 %0, %1, %2, %3;" : "=l"(d) : "l"(a), "l"(b), "l"(c));
    return d;
}
__device__ __forceinline__ ull add2(ull a, ull b) {
    ull d; asm("add.rn.f32x2 %0, %1, %2;" : "=l"(d) : "l"(a), "l"(b));
    return d;
}
__device__ __forceinline__ ull pk(float a, float b) {
    ull r; asm("mov.b64 %0, {%1, %2};" : "=l"(r)
               : "r"(__float_as_uint(a)), "r"(__float_as_uint(b)));
    return r;
}
__device__ __forceinline__ float2 upk(ull p) {
    unsigned int lo, hi;
    asm("mov.b64 {%0, %1}, %2;" : "=r"(lo), "=r"(hi) : "l"(p));
    return make_float2(__uint_as_float(lo), __uint_as_float(hi));
}
__device__ __forceinline__ float hadd(ull p) { float2 f = upk(p); return f.x + f.y; }

__device__ __forceinline__ float warp_sum(float v) {
#pragma unroll
    for (int o = 16; o; o >>= 1) v += __shfl_xor_sync(0xffffffffu, v, o);
    return v;
}

// Reduce acc[16] (each a 32-lane partial) with 16 shuffles total.
// Returns fully-reduced value for index (lane>>1)&15. (Measured win in gemm.)
__device__ __forceinline__ float reduce16_scatter(float* acc, int lane) {
#pragma unroll
    for (int step = 16, n = 8; n >= 1; step >>= 1, n >>= 1) {
        bool hi = (lane & step) != 0;
#pragma unroll
        for (int i = 0; i < n; i++) {
            float send = hi ? acc[i] : acc[i + n];
            float recv = __shfl_xor_sync(0xffffffffu, send, step);
            acc[i] = (hi ? acc[i + n] : acc[i]) + recv;
        }
    }
    float v = acc[0];
    v += __shfl_xor_sync(0xffffffffu, v, 1);
    return v;
}

// ---------------------------------------------------------------------------
// Kernel 1: attention weights. Grid 256 x 256 thr, 128 tokens/block.
// Round-2 structure (4 tokens/warp-iter, butterfly reduce, lane-0 softmax),
// dot products in packed f32x2.
// ---------------------------------------------------------------------------
__global__ __launch_bounds__(256) void k_attn(const float* __restrict__ x,
                                              const float* __restrict__ centers,
                                              const float* __restrict__ log_scales) {
    __shared__ float4 sc[Sn * 128];          // centers, 32 KB
    __shared__ float  s_inv[Sn], s_bias[Sn];

    int tid = threadIdx.x;
    for (int i = tid; i < Sn * 128; i += 256) sc[i] = ((const float4*)centers)[i];
    __syncthreads();
    if (tid < Sn) {
        float c2 = 0.f;
        for (int i = 0; i < 128; i++) {
            float4 c = sc[tid * 128 + i];
            c2 += c.x * c.x + c.y * c.y + c.z * c.z + c.w * c.w;
        }
        float s = expf(log_scales[tid]);
        s = fminf(fmaxf(s, 0.1f), 2.0f);
        float inv = -0.5f / (s * s);
        s_inv[tid]  = inv;
        s_bias[tid] = inv * c2;
    }
    __syncthreads();

    int warp = tid >> 5, lane = tid & 31;
    long long tok0 = (long long)blockIdx.x * 128;
    const float* xb = x + tok0 * Dn;

#pragma unroll 1
    for (int g = 0; g < 4; g++) {
        int tl = warp * 16 + g * 4;          // 4 tokens per iteration
        ull acc2[4][Sn];
        ull x2p[4];
#pragma unroll
        for (int i = 0; i < 4; i++) {
            x2p[i] = 0ull;
#pragma unroll
            for (int s = 0; s < Sn; s++) acc2[i][s] = 0ull;
        }
#pragma unroll
        for (int j = 0; j < 4; j++) {
            int d4 = lane + j * 32;          // 16B-chunk index into 512-wide row
            ulonglong2 xv[4];
#pragma unroll
            for (int i = 0; i < 4; i++)
                xv[i] = ((const ulonglong2*)(xb + (long long)(tl + i) * Dn))[d4];
#pragma unroll
            for (int i = 0; i < 4; i++) {
                x2p[i] = fma2(xv[i].x, xv[i].x, x2p[i]);
                x2p[i] = fma2(xv[i].y, xv[i].y, x2p[i]);
            }
#pragma unroll
            for (int s = 0; s < Sn; s++) {
                ulonglong2 cp = *(const ulonglong2*)&sc[s * 128 + d4];
#pragma unroll
                for (int i = 0; i < 4; i++) {
                    acc2[i][s] = fma2(xv[i].x, cp.x, acc2[i][s]);
                    acc2[i][s] = fma2(xv[i].y, cp.y, acc2[i][s]);
                }
            }
        }
#pragma unroll
        for (int i = 0; i < 4; i++) {
            float x2i = warp_sum(hadd(x2p[i]));
            float acc[Sn];
#pragma unroll
            for (int s = 0; s < Sn; s++) acc[s] = warp_sum(hadd(acc2[i][s]));
            if (lane == 0) {
                float l[Sn];
                float m = -1e30f;
#pragma unroll
                for (int s = 0; s < Sn; s++) {
                    l[s] = s_inv[s] * (x2i - 2.f * acc[s]) + s_bias[s];
                    m = fmaxf(m, l[s]);
                }
                float sum = 0.f;
#pragma unroll
                for (int s = 0; s < Sn; s++) { l[s] = __expf(l[s] - m); sum += l[s]; }
                float r = 1.f / sum;
                float4* dg = (float4*)(g_attn + (tok0 + tl + i) * Sn);
                dg[0] = make_float4(l[0]*r,  l[1]*r,  l[2]*r,  l[3]*r);
                dg[1] = make_float4(l[4]*r,  l[5]*r,  l[6]*r,  l[7]*r);
                dg[2] = make_float4(l[8]*r,  l[9]*r,  l[10]*r, l[11]*r);
                dg[3] = make_float4(l[12]*r, l[13]*r, l[14]*r, l[15]*r);
            }
        }
    }
}

// ---------------------------------------------------------------------------
// Kernel 2: partial G = attn^T x. Grid 256 x 256 thr, 128 tokens/block.
// Thread owns 4 dims (dg = tid&127); token range split by half = tid>>7.
// attn kept in smem as duplicated pairs {a,a}; inner loop: LDS.128 + fma2 only.
// x reread hits L2 (written by k_attn's pass over x, 64MB < 126MB L2).
// ---------------------------------------------------------------------------
__global__ __launch_bounds__(256) void k_g(const float* __restrict__ x) {
    __shared__ ull        s_a2 [128 * Sn];   // 16 KB  {a,a} pairs
    __shared__ ulonglong2 s_red[128 * Sn];   // 32 KB  cross-half reduction

    int tid = threadIdx.x;
    long long tok0 = (long long)blockIdx.x * 128;

    for (int i = tid; i < 128 * Sn; i += 256) {
        float a = g_attn[tok0 * Sn + i];
        s_a2[i] = pk(a, a);
    }
    __syncthreads();

    int dg = tid & 127, half = tid >> 7;
    const float* xb = x + (tok0 + half * 64) * Dn;

    ulonglong2 acc2[Sn];
#pragma unroll
    for (int s = 0; s < Sn; s++) { acc2[s].x = 0ull; acc2[s].y = 0ull; }

#pragma unroll 2
    for (int t = 0; t < 64; t++) {
        ulonglong2 xv = ((const ulonglong2*)(xb + (long long)t * Dn))[dg];
        const ulonglong2* ar = (const ulonglong2*)&s_a2[(half * 64 + t) * Sn];
#pragma unroll
        for (int q = 0; q < 8; q++) {
            ulonglong2 ap = ar[q];            // {a_{2q},a_{2q}}, {a_{2q+1},a_{2q+1}}
            acc2[2*q  ].x = fma2(ap.x, xv.x, acc2[2*q  ].x);
            acc2[2*q  ].y = fma2(ap.x, xv.y, acc2[2*q  ].y);
            acc2[2*q+1].x = fma2(ap.y, xv.x, acc2[2*q+1].x);
            acc2[2*q+1].y = fma2(ap.y, xv.y, acc2[2*q+1].y);
        }
    }

    if (half == 1) {
#pragma unroll
        for (int s = 0; s < Sn; s++) s_red[s * 128 + dg] = acc2[s];
    }
    __syncthreads();
    if (half == 0) {
        int b = (int)(tok0 / Tn);
        int p = (int)((tok0 % Tn) / 128);
        float* gp = g_Gpart + ((long long)(b * PARTS + p) * Sn * Dn);
#pragma unroll
        for (int s = 0; s < Sn; s++) {
            ulonglong2 o = s_red[s * 128 + dg];
            acc2[s].x = add2(acc2[s].x, o.x);
            acc2[s].y = add2(acc2[s].y, o.y);
            ((ulonglong2*)(gp + s * Dn))[dg] = acc2[s];
        }
    }
}

// ---------------------------------------------------------------------------
// Kernel 3: reduce 64 partials -> G. 32768 outputs. Grid 128 x 256 thr.
// ---------------------------------------------------------------------------
__global__ void k_reduce() {
    int idx = blockIdx.x * blockDim.x + threadIdx.x;   // < Bn*Sn*Dn = 32768
    int b = idx >> 13;
    int r = idx & 8191;
    float sum = 0.f;
#pragma unroll
    for (int p = 0; p < PARTS; p++)
        sum += g_Gpart[(long long)(b * PARTS + p) * (Sn * Dn) + r];
    g_G[idx] = sum;
}

// ---------------------------------------------------------------------------
// Kernel 4: small GEMM out[row][k] = sum_d in[row][d] * W[k][d], rows = 64.
// Grid (64,4) x 256 thr; 16 in-rows in smem; warp-per-column; f32x2 inner;
// reduce-scatter finish (measured faster than butterfly here).
// ---------------------------------------------------------------------------
__global__ __launch_bounds__(256) void k_small_gemm(const float* __restrict__ W, int stage) {
    const float* in  = (stage == 0) ? g_G : g_H;
    float*       out = (stage == 0) ? g_H : g_M;
    __shared__ float4 s_in[16 * 128];        // 32 KB

    int tid = threadIdx.x, warp = tid >> 5, lane = tid & 31;
    int kc = blockIdx.x;                     // 0..63 column chunk
    int b  = blockIdx.y;                     // 0..3 batch

    const float4* src = (const float4*)(in + (long long)b * 16 * Dn);
#pragma unroll
    for (int i = 0; i < 8; i++) s_in[tid + i * 256] = src[tid + i * 256];
    __syncthreads();

    int k = kc * 8 + warp;                   // output column, 0..511
    const ulonglong2* wr = (const ulonglong2*)(W + (long long)k * Dn);
    ulonglong2 w0 = wr[lane], w1 = wr[lane + 32], w2 = wr[lane + 64], w3 = wr[lane + 96];

    float acc[16];
#pragma unroll
    for (int r = 0; r < 16; r++) {
        ulonglong2 g0 = *(const ulonglong2*)&s_in[r * 128 + lane];
        ulonglong2 g1 = *(const ulonglong2*)&s_in[r * 128 + lane + 32];
        ulonglong2 g2 = *(const ulonglong2*)&s_in[r * 128 + lane + 64];
        ulonglong2 g3 = *(const ulonglong2*)&s_in[r * 128 + lane + 96];
        ull a = fma2(w0.x, g0.x, 0ull);
        a = fma2(w0.y, g0.y, a);
        a = fma2(w1.x, g1.x, a);
        a = fma2(w1.y, g1.y, a);
        a = fma2(w2.x, g2.x, a);
        a = fma2(w2.y, g2.y, a);
        a = fma2(w3.x, g3.x, a);
        a = fma2(w3.y, g3.y, a);
        acc[r] = hadd(a);
    }
    float val = reduce16_scatter(acc, lane);
    int row = (lane >> 1) & 15;
    if ((lane & 1) == 0)
        out[(long long)(b * 16 + row) * Dn + k] = val;
}

// ---------------------------------------------------------------------------
// Kernel 5: y[t,:] = sum_s attn[t,s] * M[b,s,:]. Grid 256 x 256 thr,
// 128 tokens/block, thread owns 4 dims, token halves; M in regs as pairs.
// ---------------------------------------------------------------------------
__global__ __launch_bounds__(256) void k_out(float* __restrict__ y) {
    __shared__ ull s_a2[128 * Sn];           // 16 KB {a,a}
    int tid = threadIdx.x;
    long long tok0 = (long long)blockIdx.x * 128;
    int b = (int)(tok0 / Tn);

    for (int i = tid; i < 128 * Sn; i += 256) {
        float a = g_attn[tok0 * Sn + i];
        s_a2[i] = pk(a, a);
    }
    __syncthreads();

    int dg = tid & 127, half = tid >> 7;
    const float* Mb = g_M + (long long)b * Sn * Dn;
    ulonglong2 m2[Sn];
#pragma unroll
    for (int s = 0; s < Sn; s++) m2[s] = ((const ulonglong2*)(Mb + s * Dn))[dg];

    float* yb = y + (tok0 + half * 64) * Dn;
#pragma unroll 2
    for (int t = 0; t < 64; t++) {
        const ulonglong2* ar = (const ulonglong2*)&s_a2[(half * 64 + t) * Sn];
        ull ox = 0ull, oy = 0ull;             // dims {0,1} and {2,3}
#pragma unroll
        for (int q = 0; q < 8; q++) {
            ulonglong2 ap = ar[q];
            ox = fma2(ap.x, m2[2*q  ].x, ox);
            oy = fma2(ap.x, m2[2*q  ].y, oy);
            ox = fma2(ap.y, m2[2*q+1].x, ox);
            oy = fma2(ap.y, m2[2*q+1].y, oy);
        }
        ulonglong2 o; o.x = ox; o.y = oy;
        ((ulonglong2*)(yb + (long long)t * Dn))[dg] = o;
    }
}

// ---------------------------------------------------------------------------
extern "C" void kernel_launch(void* const* d_in, const int* in_sizes, int n_in,
                              void* d_out, int out_size) {
    (void)in_sizes; (void)n_in; (void)out_size;
    const float* x          = (const float*)d_in[0];   // [B,T,D]
    const float* centers    = (const float*)d_in[1];   // [S,D]
    const float* log_scales = (const float*)d_in[2];   // [S]
    const float* Wv         = (const float*)d_in[3];   // [D,D]
    const float* Wo         = (const float*)d_in[4];   // [D,D]
    float* y = (float*)d_out;                          // [B,T,D] fp32

    k_attn<<<256, 256>>>(x, centers, log_scales);
    k_g<<<256, 256>>>(x);
    k_reduce<<<128, 256>>>();
    k_small_gemm<<<dim3(64, 4), 256>>>(Wv, 0);
    k_small_gemm<<<dim3(64, 4), 256>>>(Wo, 1);
    k_out<<<256, 256>>>(y);
}

// round 5
// speedup vs baseline: 1.5640x; 1.5640x over previous
#include <cuda_runtime.h>
#include <math.h>

#define Bn 4
#define Tn 8192
#define Dn 512
#define Sn 16
#define PARTS 64   // 256 blocks / 4 batches in the fused attn+G pass

// Scratch (static device globals — allocation-free per harness rules)
__device__ float g_attn [Bn*Tn*Sn];          // 2 MB
__device__ float g_Gpart[Bn*PARTS*Sn*Dn];    // 8 MB
__device__ float g_G    [Bn*Sn*Dn];
__device__ float g_H    [Bn*Sn*Dn];
__device__ float g_M    [Bn*Sn*Dn];

// 8-lane reduction (within group: lanes differing in bits 0..2)
__device__ __forceinline__ float red8(float v) {
    v += __shfl_xor_sync(0xffffffffu, v, 1);
    v += __shfl_xor_sync(0xffffffffu, v, 2);
    v += __shfl_xor_sync(0xffffffffu, v, 4);
    return v;
}

// Reduce acc[16] (each a 32-lane partial) with 16 shuffles total.
// Returns fully-reduced value for index (lane>>1)&15. (Measured win in k_small_gemm.)
__device__ __forceinline__ float reduce16_scatter(float* acc, int lane) {
#pragma unroll
    for (int step = 16, n = 8; n >= 1; step >>= 1, n >>= 1) {
        bool hi = (lane & step) != 0;
#pragma unroll
        for (int i = 0; i < n; i++) {
            float send = hi ? acc[i] : acc[i + n];
            float recv = __shfl_xor_sync(0xffffffffu, send, step);
            acc[i] = (hi ? acc[i + n] : acc[i]) + recv;
        }
    }
    float v = acc[0];
    v += __shfl_xor_sync(0xffffffffu, v, 1);
    return v;
}

// ---------------------------------------------------------------------------
// Kernel 1 (fused): attention weights + partial G = attn^T x.
// Grid 256 blocks x 256 thr, 128 tokens/block.
// Phase 1: warp = 4 groups of 8 lanes; each group owns 4 tokens, lanes split
//          D 8-ways. 3-stage group reduction (204 shfl / 16 tokens) and
//          distributed softmax (2 lanes per token, each stores 8 outputs).
// Phase 2: thread owns d-pair, fixed-order token loop -> G partial.
// ---------------------------------------------------------------------------
__global__ __launch_bounds__(256) void k_attn_g(const float* __restrict__ x,
                                                const float* __restrict__ centers,
                                                const float* __restrict__ log_scales) {
    __shared__ float4 sc[Sn * 128];          // centers, 32 KB
    __shared__ float  s_attn[128 * Sn];      // 8 KB attn tile for phase 2
    __shared__ float  s_inv[Sn], s_bias[Sn];

    int tid = threadIdx.x;
    for (int i = tid; i < Sn * 128; i += 256) sc[i] = ((const float4*)centers)[i];
    __syncthreads();
    if (tid < Sn) {
        float c2 = 0.f;
        for (int i = 0; i < 128; i++) {
            float4 c = sc[tid * 128 + i];
            c2 += c.x * c.x + c.y * c.y + c.z * c.z + c.w * c.w;
        }
        float s = expf(log_scales[tid]);
        s = fminf(fmaxf(s, 0.1f), 2.0f);
        float inv = -0.5f / (s * s);
        s_inv[tid]  = inv;
        s_bias[tid] = inv * c2;
    }
    __syncthreads();

    int warp = tid >> 5, lane = tid & 31;
    int grp  = lane >> 3, li = lane & 7;
    long long tok0 = (long long)blockIdx.x * 128;
    const float* xb = x + tok0 * Dn;

    // -------- Phase 1: 16 tokens per warp, 4 per 8-lane group --------
    int tl = warp * 16 + grp * 4;            // group's first token
    float acc[4][Sn];
    float x2[4];
#pragma unroll
    for (int i = 0; i < 4; i++) {
        x2[i] = 0.f;
#pragma unroll
        for (int s = 0; s < Sn; s++) acc[i][s] = 0.f;
    }

#pragma unroll 4
    for (int j = 0; j < 16; j++) {
        int d4 = li + j * 8;                 // float4 chunk (lane covers 16 of 128)
        float4 xv[4];
#pragma unroll
        for (int i = 0; i < 4; i++)
            xv[i] = ((const float4*)(xb + (long long)(tl + i) * Dn))[d4];
#pragma unroll
        for (int i = 0; i < 4; i++)
            x2[i] += xv[i].x * xv[i].x + xv[i].y * xv[i].y +
                     xv[i].z * xv[i].z + xv[i].w * xv[i].w;
#pragma unroll
        for (int s = 0; s < Sn; s++) {
            float4 c = sc[s * 128 + d4];
#pragma unroll
            for (int i = 0; i < 4; i++)
                acc[i][s] += xv[i].x * c.x + xv[i].y * c.y +
                             xv[i].z * c.z + xv[i].w * c.w;
        }
    }

    // 3-stage reduction over the 8 lanes of the group (all values end replicated)
#pragma unroll
    for (int i = 0; i < 4; i++) {
        x2[i] = red8(x2[i]);
#pragma unroll
        for (int s = 0; s < Sn; s++) acc[i][s] = red8(acc[i][s]);
    }

    // Distributed softmax: lane li handles token (li>>1), half (li&1)
    {
        int tok = li >> 1;                   // 0..3
        int hsel = (li & 1) * 8;             // output offset 0 or 8
        float l[Sn];
        float m = -1e30f;
#pragma unroll
        for (int s = 0; s < Sn; s++) {
            l[s] = s_inv[s] * (x2[tok] - 2.f * acc[tok][s]) + s_bias[s];
            m = fmaxf(m, l[s]);
        }
        float sum = 0.f;
#pragma unroll
        for (int s = 0; s < Sn; s++) { l[s] = __expf(l[s] - m); sum += l[s]; }
        float r = 1.f / sum;
        float4 va = make_float4(l[hsel+0]*r, l[hsel+1]*r, l[hsel+2]*r, l[hsel+3]*r);
        float4 vb = make_float4(l[hsel+4]*r, l[hsel+5]*r, l[hsel+6]*r, l[hsel+7]*r);
        long long t = tl + tok;
        float4* dg = (float4*)(g_attn + (tok0 + t) * Sn + hsel);
        dg[0] = va; dg[1] = vb;
        float4* ds = (float4*)(s_attn + t * Sn + hsel);
        ds[0] = va; ds[1] = vb;
    }
    __syncthreads();

    // -------- Phase 2: G partial over this block's 128 tokens --------
    float2 accG[Sn];
#pragma unroll
    for (int s = 0; s < Sn; s++) { accG[s].x = 0.f; accG[s].y = 0.f; }

#pragma unroll 4
    for (int t = 0; t < 128; t++) {
        float2 xv = ((const float2*)(xb + (long long)t * Dn))[tid];   // d = 2*tid, 2*tid+1
        const float4* ar = (const float4*)&s_attn[t * Sn];
#pragma unroll
        for (int q = 0; q < 4; q++) {
            float4 a = ar[q];
            accG[q*4+0].x += a.x * xv.x; accG[q*4+0].y += a.x * xv.y;
            accG[q*4+1].x += a.y * xv.x; accG[q*4+1].y += a.y * xv.y;
            accG[q*4+2].x += a.z * xv.x; accG[q*4+2].y += a.z * xv.y;
            accG[q*4+3].x += a.w * xv.x; accG[q*4+3].y += a.w * xv.y;
        }
    }

    int b = (int)(tok0 / Tn);
    int p = (int)((tok0 % Tn) / 128);
    float* gp = g_Gpart + ((long long)(b * PARTS + p) * Sn * Dn);
#pragma unroll
    for (int s = 0; s < Sn; s++)
        ((float2*)(gp + s * Dn))[tid] = accG[s];
}

// ---------------------------------------------------------------------------
// Kernel 2: reduce 64 partials -> G. 32768 outputs. Grid 128 x 256 thr.
// ---------------------------------------------------------------------------
__global__ void k_reduce() {
    int idx = blockIdx.x * blockDim.x + threadIdx.x;   // < Bn*Sn*Dn = 32768
    int b = idx >> 13;
    int r = idx & 8191;
    float sum = 0.f;
#pragma unroll
    for (int p = 0; p < PARTS; p++)
        sum += g_Gpart[(long long)(b * PARTS + p) * (Sn * Dn) + r];
    g_G[idx] = sum;
}

// ---------------------------------------------------------------------------
// Kernel 3: small GEMM out[row][k] = sum_d in[row][d] * W[k][d], rows = 64.
// Round-3 version (measured 7.46us): 16 in-rows in smem, warp-per-column,
// plain float4 FMA, reduce-scatter finish.
// ---------------------------------------------------------------------------
__global__ __launch_bounds__(256) void k_small_gemm(const float* __restrict__ W, int stage) {
    const float* in  = (stage == 0) ? g_G : g_H;
    float*       out = (stage == 0) ? g_H : g_M;
    __shared__ float4 s_in[16 * 128];        // 32 KB

    int tid = threadIdx.x, warp = tid >> 5, lane = tid & 31;
    int kc = blockIdx.x;                     // 0..63 column chunk
    int b  = blockIdx.y;                     // 0..3 batch

    const float4* src = (const float4*)(in + (long long)b * 16 * Dn);
#pragma unroll
    for (int i = 0; i < 8; i++) s_in[tid + i * 256] = src[tid + i * 256];
    __syncthreads();

    int k = kc * 8 + warp;                   // output column, 0..511
    const float4* wr = (const float4*)(W + (long long)k * Dn);
    float4 w0 = wr[lane], w1 = wr[lane + 32], w2 = wr[lane + 64], w3 = wr[lane + 96];

    float acc[16];
#pragma unroll
    for (int r = 0; r < 16; r++) {
        float4 g0 = s_in[r * 128 + lane];
        float4 g1 = s_in[r * 128 + lane + 32];
        float4 g2 = s_in[r * 128 + lane + 64];
        float4 g3 = s_in[r * 128 + lane + 96];
        acc[r] = w0.x*g0.x + w0.y*g0.y + w0.z*g0.z + w0.w*g0.w
               + w1.x*g1.x + w1.y*g1.y + w1.z*g1.z + w1.w*g1.w
               + w2.x*g2.x + w2.y*g2.y + w2.z*g2.z + w2.w*g2.w
               + w3.x*g3.x + w3.y*g3.y + w3.z*g3.z + w3.w*g3.w;
    }
    float val = reduce16_scatter(acc, lane);
    int row = (lane >> 1) & 15;
    if ((lane & 1) == 0)
        out[(long long)(b * 16 + row) * Dn + k] = val;
}

// ---------------------------------------------------------------------------
// Kernel 4: y[t,:] = sum_s attn[t,s] * M[b,s,:]. Round-2 version.
// Grid 512 x 256 thr, 64 tokens/block; M columns in registers; float2 stores.
// ---------------------------------------------------------------------------
__global__ __launch_bounds__(256) void k_out(float* __restrict__ y) {
    __shared__ float s_a[64 * Sn];           // 4 KB attn tile
    int tid = threadIdx.x;
    long long tok0 = (long long)blockIdx.x * 64;
    int b = (int)(tok0 / Tn);

    ((float4*)s_a)[tid] = ((const float4*)(g_attn + tok0 * Sn))[tid];  // 256 float4
    __syncthreads();

    const float* Mb = g_M + (long long)b * Sn * Dn;
    float2 m[Sn];
#pragma unroll
    for (int s = 0; s < Sn; s++) m[s] = ((const float2*)(Mb + s * Dn))[tid];

    float* yb = y + tok0 * Dn;
#pragma unroll 2
    for (int t = 0; t < 64; t++) {
        const float4* ar = (const float4*)&s_a[t * Sn];
        float2 o; o.x = 0.f; o.y = 0.f;
#pragma unroll
        for (int q = 0; q < 4; q++) {
            float4 a = ar[q];
            o.x += a.x * m[q*4+0].x + a.y * m[q*4+1].x + a.z * m[q*4+2].x + a.w * m[q*4+3].x;
            o.y += a.x * m[q*4+0].y + a.y * m[q*4+1].y + a.z * m[q*4+2].y + a.w * m[q*4+3].y;
        }
        ((float2*)(yb + (long long)t * Dn))[tid] = o;
    }
}

// ---------------------------------------------------------------------------
extern "C" void kernel_launch(void* const* d_in, const int* in_sizes, int n_in,
                              void* d_out, int out_size) {
    (void)in_sizes; (void)n_in; (void)out_size;
    const float* x          = (const float*)d_in[0];   // [B,T,D]
    const float* centers    = (const float*)d_in[1];   // [S,D]
    const float* log_scales = (const float*)d_in[2];   // [S]
    const float* Wv         = (const float*)d_in[3];   // [D,D]
    const float* Wo         = (const float*)d_in[4];   // [D,D]
    float* y = (float*)d_out;                          // [B,T,D] fp32

    k_attn_g<<<256, 256>>>(x, centers, log_scales);
    k_reduce<<<128, 256>>>();
    k_small_gemm<<<dim3(64, 4), 256>>>(Wv, 0);
    k_small_gemm<<<dim3(64, 4), 256>>>(Wo, 1);
    k_out<<<512, 256>>>(y);
}

// round 6
// speedup vs baseline: 1.9537x; 1.2491x over previous
#include <cuda_runtime.h>
#include <math.h>

#define Bn 4
#define Tn 8192
#define Dn 512
#define Sn 16
#define PARTS 64   // 256 blocks / 4 batches in the fused attn+G pass

// Scratch (static device globals — allocation-free per harness rules)
__device__ float g_attn [Bn*Tn*Sn];          // 2 MB
__device__ float g_Gpart[Bn*PARTS*Sn*Dn];    // 8 MB
__device__ float g_G    [Bn*Sn*Dn];
__device__ float g_H    [Bn*Sn*Dn];
__device__ float g_M    [Bn*Sn*Dn];

__device__ __forceinline__ unsigned f2tf32(float f) {
    unsigned r; asm("cvt.rna.tf32.f32 %0, %1;" : "=r"(r) : "f"(f));
    return r;
}

__device__ __forceinline__ void mma_tf32(float c[4],
    unsigned a0, unsigned a1, unsigned a2, unsigned a3,
    unsigned b0, unsigned b1) {
    asm("mma.sync.aligned.m16n8k8.row.col.f32.tf32.tf32.f32 "
        "{%0,%1,%2,%3}, {%4,%5,%6,%7}, {%8,%9}, {%0,%1,%2,%3};"
        : "+f"(c[0]), "+f"(c[1]), "+f"(c[2]), "+f"(c[3])
        : "r"(a0), "r"(a1), "r"(a2), "r"(a3), "r"(b0), "r"(b1));
}

// 8-lane reduction (lanes differing in bits 0..2)
__device__ __forceinline__ float red8(float v) {
    v += __shfl_xor_sync(0xffffffffu, v, 1);
    v += __shfl_xor_sync(0xffffffffu, v, 2);
    v += __shfl_xor_sync(0xffffffffu, v, 4);
    return v;
}

// Reduce acc[16] with 16 shuffles; result for index (lane>>1)&15 on even lanes.
__device__ __forceinline__ float reduce16_scatter(float* acc, int lane) {
#pragma unroll
    for (int step = 16, n = 8; n >= 1; step >>= 1, n >>= 1) {
        bool hi = (lane & step) != 0;
#pragma unroll
        for (int i = 0; i < n; i++) {
            float send = hi ? acc[i] : acc[i + n];
            float recv = __shfl_xor_sync(0xffffffffu, send, step);
            acc[i] = (hi ? acc[i + n] : acc[i]) + recv;
        }
    }
    float v = acc[0];
    v += __shfl_xor_sync(0xffffffffu, v, 1);
    return v;
}

// ---------------------------------------------------------------------------
// Kernel 1 (fused): attention weights (tf32 MMA for xc, fp32 x2/softmax)
// + partial G = attn^T x (fp32). Grid 256 x 256 thr, 128 tokens/block.
// ---------------------------------------------------------------------------
__global__ __launch_bounds__(256) void k_attn_g(const float* __restrict__ x,
                                                const float* __restrict__ centers,
                                                const float* __restrict__ log_scales) {
    __shared__ float    s_x   [128 * 36];    // tf32 x chunk, padded (18 KB)
    __shared__ unsigned s_bf  [512];         // B fragments for current chunk (2 KB)
    __shared__ float    s_xc  [128 * 17];    // XC, padded (8.7 KB)
    __shared__ float    s_attn[128 * Sn];    // 8 KB
    __shared__ float    s_x2  [128];
    __shared__ float    s_part[256];
    __shared__ float    s_inv [Sn], s_bias[Sn];

    int tid  = threadIdx.x;
    int warp = tid >> 5, lane = tid & 31;
    int gid  = lane >> 2, tg = lane & 3;     // mma fragment coords
    int grp  = lane >> 3, li = lane & 7;     // x2 groups
    long long tok0 = (long long)blockIdx.x * 128;
    const float* xb = x + tok0 * Dn;

    // ---- scale/bias precompute: c2 via 16 threads per splat ----
    {
        int sp = tid >> 4, p16 = tid & 15;
        const float4* cr = (const float4*)(centers + (long long)sp * Dn);
        float c2 = 0.f;
#pragma unroll
        for (int j = 0; j < 8; j++) {
            float4 v = cr[p16 + j * 16];
            c2 += v.x * v.x + v.y * v.y + v.z * v.z + v.w * v.w;
        }
        s_part[tid] = c2;
        __syncthreads();
        if (tid < Sn) {
            float c2t = 0.f;
#pragma unroll
            for (int k = 0; k < 16; k++) c2t += s_part[tid * 16 + k];
            float s = expf(log_scales[tid]);
            s = fminf(fmaxf(s, 0.1f), 2.0f);
            float inv = -0.5f / (s * s);
            s_inv[tid]  = inv;
            s_bias[tid] = inv * c2t;
        }
    }

    // ---- Phase 1: XC = x . centers^T via tf32 mma, x2 in fp32 ----
    float xcacc[2][4];
#pragma unroll
    for (int h = 0; h < 2; h++)
#pragma unroll
        for (int r = 0; r < 4; r++) xcacc[h][r] = 0.f;
    float x2r[4] = {0.f, 0.f, 0.f, 0.f};
    int tlw = warp * 16;                     // warp's m-tile token base
    int tlg = tlw + grp * 4;                 // x2 group token base

#pragma unroll 1
    for (int c = 0; c < 16; c++) {
        // stage x chunk (cols c*32..+31) as tf32, padded stride 36
#pragma unroll
        for (int i = 0; i < 4; i++) {
            int idx = tid + i * 256;         // 0..1023 = 128 rows x 8 float4
            int row = idx >> 3, c4 = idx & 7;
            float4 v = ((const float4*)(xb + (long long)row * Dn))[c * 8 + c4];
            float4 t;
            t.x = __uint_as_float(f2tf32(v.x));
            t.y = __uint_as_float(f2tf32(v.y));
            t.z = __uint_as_float(f2tf32(v.z));
            t.w = __uint_as_float(f2tf32(v.w));
            *(float4*)&s_x[row * 36 + c4 * 4] = t;
        }
        // B fragments for this chunk: [kit8][h][which][lane]
#pragma unroll
        for (int i = 0; i < 2; i++) {
            int e = tid + i * 256;           // 0..511
            int kit8 = e >> 7, rem = e & 127;
            int h = rem >> 6, which = (rem >> 5) & 1, L = rem & 31;
            int k  = c * 32 + kit8 * 8 + (L & 3) + which * 4;
            int sp = h * 8 + (L >> 2);
            s_bf[e] = f2tf32(centers[(long long)sp * Dn + k]);
        }
        // x2 partials from gmem (lines are L1-hot from staging)
#pragma unroll
        for (int i = 0; i < 4; i++) {
            float4 v = ((const float4*)(xb + (long long)(tlg + i) * Dn))[c * 8 + li];
            x2r[i] += v.x * v.x + v.y * v.y + v.z * v.z + v.w * v.w;
        }
        __syncthreads();
        // 4 k-iterations of m16n8k8 per n-half
#pragma unroll
        for (int kit8 = 0; kit8 < 4; kit8++) {
            int kb = kit8 * 8;
            unsigned a0 = __float_as_uint(s_x[(tlw + gid)     * 36 + kb + tg]);
            unsigned a1 = __float_as_uint(s_x[(tlw + gid + 8) * 36 + kb + tg]);
            unsigned a2 = __float_as_uint(s_x[(tlw + gid)     * 36 + kb + tg + 4]);
            unsigned a3 = __float_as_uint(s_x[(tlw + gid + 8) * 36 + kb + tg + 4]);
#pragma unroll
            for (int h = 0; h < 2; h++) {
                unsigned b0 = s_bf[kit8 * 128 + h * 64 + lane];
                unsigned b1 = s_bf[kit8 * 128 + h * 64 + 32 + lane];
                mma_tf32(xcacc[h], a0, a1, a2, a3, b0, b1);
            }
        }
        __syncthreads();
    }

    // write XC fragments to padded smem
#pragma unroll
    for (int h = 0; h < 2; h++) {
        int col = h * 8 + tg * 2;
        s_xc[(tlw + gid)     * 17 + col]     = xcacc[h][0];
        s_xc[(tlw + gid)     * 17 + col + 1] = xcacc[h][1];
        s_xc[(tlw + gid + 8) * 17 + col]     = xcacc[h][2];
        s_xc[(tlw + gid + 8) * 17 + col + 1] = xcacc[h][3];
    }
#pragma unroll
    for (int i = 0; i < 4; i++) x2r[i] = red8(x2r[i]);
    if (li < 4) s_x2[tlg + li] = x2r[li];
    __syncthreads();

    // per-token softmax (threads 0..127)
    if (tid < 128) {
        float x2 = s_x2[tid];
        float l[Sn];
        float m = -1e30f;
#pragma unroll
        for (int s = 0; s < Sn; s++) {
            l[s] = s_inv[s] * (x2 - 2.f * s_xc[tid * 17 + s]) + s_bias[s];
            m = fmaxf(m, l[s]);
        }
        float sum = 0.f;
#pragma unroll
        for (int s = 0; s < Sn; s++) { l[s] = __expf(l[s] - m); sum += l[s]; }
        float r = 1.f / sum;
#pragma unroll
        for (int s = 0; s < Sn; s++) s_attn[tid * Sn + s] = l[s] * r;
    }
    __syncthreads();

    // coalesced copy s_attn -> g_attn
    for (int i = tid; i < 128 * Sn / 4; i += 256)
        ((float4*)(g_attn + tok0 * Sn))[i] = ((const float4*)s_attn)[i];

    // -------- Phase 2: G partial over this block's 128 tokens (fp32) --------
    float2 accG[Sn];
#pragma unroll
    for (int s = 0; s < Sn; s++) { accG[s].x = 0.f; accG[s].y = 0.f; }

#pragma unroll 4
    for (int t = 0; t < 128; t++) {
        float2 xv = ((const float2*)(xb + (long long)t * Dn))[tid];   // d = 2*tid, 2*tid+1
        const float4* ar = (const float4*)&s_attn[t * Sn];
#pragma unroll
        for (int q = 0; q < 4; q++) {
            float4 a = ar[q];
            accG[q*4+0].x += a.x * xv.x; accG[q*4+0].y += a.x * xv.y;
            accG[q*4+1].x += a.y * xv.x; accG[q*4+1].y += a.y * xv.y;
            accG[q*4+2].x += a.z * xv.x; accG[q*4+2].y += a.z * xv.y;
            accG[q*4+3].x += a.w * xv.x; accG[q*4+3].y += a.w * xv.y;
        }
    }

    int b = (int)(tok0 / Tn);
    int p = (int)((tok0 % Tn) / 128);
    float* gp = g_Gpart + ((long long)(b * PARTS + p) * Sn * Dn);
#pragma unroll
    for (int s = 0; s < Sn; s++)
        ((float2*)(gp + s * Dn))[tid] = accG[s];
}

// ---------------------------------------------------------------------------
// Kernel 2: reduce 64 partials -> G. 32768 outputs. Grid 128 x 256 thr.
// ---------------------------------------------------------------------------
__global__ void k_reduce() {
    int idx = blockIdx.x * blockDim.x + threadIdx.x;   // < Bn*Sn*Dn = 32768
    int b = idx >> 13;
    int r = idx & 8191;
    float sum = 0.f;
#pragma unroll
    for (int p = 0; p < PARTS; p++)
        sum += g_Gpart[(long long)(b * PARTS + p) * (Sn * Dn) + r];
    g_G[idx] = sum;
}

// ---------------------------------------------------------------------------
// Kernel 3: small GEMM out[row][k] = sum_d in[row][d] * W[k][d], rows = 64.
// (measured 7.4us) 16 in-rows in smem, warp-per-column, reduce-scatter finish.
// ---------------------------------------------------------------------------
__global__ __launch_bounds__(256) void k_small_gemm(const float* __restrict__ W, int stage) {
    const float* in  = (stage == 0) ? g_G : g_H;
    float*       out = (stage == 0) ? g_H : g_M;
    __shared__ float4 s_in[16 * 128];        // 32 KB

    int tid = threadIdx.x, warp = tid >> 5, lane = tid & 31;
    int kc = blockIdx.x;                     // 0..63 column chunk
    int b  = blockIdx.y;                     // 0..3 batch

    const float4* src = (const float4*)(in + (long long)b * 16 * Dn);
#pragma unroll
    for (int i = 0; i < 8; i++) s_in[tid + i * 256] = src[tid + i * 256];
    __syncthreads();

    int k = kc * 8 + warp;                   // output column, 0..511
    const float4* wr = (const float4*)(W + (long long)k * Dn);
    float4 w0 = wr[lane], w1 = wr[lane + 32], w2 = wr[lane + 64], w3 = wr[lane + 96];

    float acc[16];
#pragma unroll
    for (int r = 0; r < 16; r++) {
        float4 g0 = s_in[r * 128 + lane];
        float4 g1 = s_in[r * 128 + lane + 32];
        float4 g2 = s_in[r * 128 + lane + 64];
        float4 g3 = s_in[r * 128 + lane + 96];
        acc[r] = w0.x*g0.x + w0.y*g0.y + w0.z*g0.z + w0.w*g0.w
               + w1.x*g1.x + w1.y*g1.y + w1.z*g1.z + w1.w*g1.w
               + w2.x*g2.x + w2.y*g2.y + w2.z*g2.z + w2.w*g2.w
               + w3.x*g3.x + w3.y*g3.y + w3.z*g3.z + w3.w*g3.w;
    }
    float val = reduce16_scatter(acc, lane);
    int row = (lane >> 1) & 15;
    if ((lane & 1) == 0)
        out[(long long)(b * 16 + row) * Dn + k] = val;
}

// ---------------------------------------------------------------------------
// Kernel 4: y[t,:] = sum_s attn[t,s] * M[b,s,:]. Grid 512 x 256 thr,
// 64 tokens/block; M columns in registers; float2 stores.
// ---------------------------------------------------------------------------
__global__ __launch_bounds__(256) void k_out(float* __restrict__ y) {
    __shared__ float s_a[64 * Sn];           // 4 KB attn tile
    int tid = threadIdx.x;
    long long tok0 = (long long)blockIdx.x * 64;
    int b = (int)(tok0 / Tn);

    ((float4*)s_a)[tid] = ((const float4*)(g_attn + tok0 * Sn))[tid];  // 256 float4
    __syncthreads();

    const float* Mb = g_M + (long long)b * Sn * Dn;
    float2 m[Sn];
#pragma unroll
    for (int s = 0; s < Sn; s++) m[s] = ((const float2*)(Mb + s * Dn))[tid];

    float* yb = y + tok0 * Dn;
#pragma unroll 2
    for (int t = 0; t < 64; t++) {
        const float4* ar = (const float4*)&s_a[t * Sn];
        float2 o; o.x = 0.f; o.y = 0.f;
#pragma unroll
        for (int q = 0; q < 4; q++) {
            float4 a = ar[q];
            o.x += a.x * m[q*4+0].x + a.y * m[q*4+1].x + a.z * m[q*4+2].x + a.w * m[q*4+3].x;
            o.y += a.x * m[q*4+0].y + a.y * m[q*4+1].y + a.z * m[q*4+2].y + a.w * m[q*4+3].y;
        }
        ((float2*)(yb + (long long)t * Dn))[tid] = o;
    }
}

// ---------------------------------------------------------------------------
extern "C" void kernel_launch(void* const* d_in, const int* in_sizes, int n_in,
                              void* d_out, int out_size) {
    (void)in_sizes; (void)n_in; (void)out_size;
    const float* x          = (const float*)d_in[0];   // [B,T,D]
    const float* centers    = (const float*)d_in[1];   // [S,D]
    const float* log_scales = (const float*)d_in[2];   // [S]
    const float* Wv         = (const float*)d_in[3];   // [D,D]
    const float* Wo         = (const float*)d_in[4];   // [D,D]
    float* y = (float*)d_out;                          // [B,T,D] fp32

    k_attn_g<<<256, 256>>>(x, centers, log_scales);
    k_reduce<<<128, 256>>>();
    k_small_gemm<<<dim3(64, 4), 256>>>(Wv, 0);
    k_small_gemm<<<dim3(64, 4), 256>>>(Wo, 1);
    k_out<<<512, 256>>>(y);
}